// round 14
// baseline (speedup 1.0000x reference)
#include <cuda_runtime.h>
#include <cuda_fp16.h>
#include <cstdint>

// Problem constants
#define BB 2
#define LL 4096
#define CC 512
#define HH 8
#define KK 13
#define DH 64
#define RR 6              // K/2
#define NBIAS 25          // 2K-1
#define SCALE 0.125f      // DH^-0.5

#define M_TOTAL (BB * LL)   // 8192 rows per GEMM

// GEMM tiling: 128x128 tile, BK=32, 3-stage cp.async, 256 threads (8 warps 2x4)
#define BKD 32
#define A_STRIDE_F 40       // fp32 A: floats/row; 160B
#define A_STRIDE_H 40       // fp16 A: halfs/row; 80B
#define B_STRIDE_H 40       // fp16 B: halfs/row; 80B
#define STAGES 3
#define A_STAGE_F (128 * A_STRIDE_F)   // 5120 floats (20480 B)
#define A_STAGE_H (128 * A_STRIDE_H)   // 5120 halfs  (10240 B)
#define B_STAGE_H (128 * B_STRIDE_H)   // 5120 halfs  (10240 B)
#define SMEM_BYTES_F32A (STAGES * (A_STAGE_F * 4 + B_STAGE_H * 2))  // 92160
#define SMEM_BYTES_F16A (STAGES * (A_STAGE_H * 2 + B_STAGE_H * 2))  // 61440

// ---------------------------------------------------------------------------
// Scratch (no cudaMalloc). cp.async global sources must be 16B-aligned.
// ---------------------------------------------------------------------------
__device__ __align__(16) __half g_qh[M_TOTAL * CC];
__device__ __align__(16) __half g_kh[M_TOTAL * CC];
__device__ __align__(16) __half g_vh[M_TOTAL * CC];
__device__ __align__(16) __half g_att[M_TOTAL * CC];
__device__ __align__(16) __half g_wt[4][CC * CC];   // fp16 weights, transposed [N][K]

// ---------------------------------------------------------------------------
// Helpers
// ---------------------------------------------------------------------------
__device__ __forceinline__ uint32_t pack_h2(float lo, float hi) {
    __half2 h = __floats2half2_rn(lo, hi);
    return *reinterpret_cast<uint32_t*>(&h);
}

__device__ __forceinline__ void mma_f16(float& c0, float& c1, float& c2, float& c3,
                                        uint32_t a0, uint32_t a1, uint32_t a2, uint32_t a3,
                                        uint32_t b0, uint32_t b1) {
    asm volatile(
        "mma.sync.aligned.m16n8k16.row.col.f32.f16.f16.f32 "
        "{%0,%1,%2,%3}, {%4,%5,%6,%7}, {%8,%9}, {%0,%1,%2,%3};"
        : "+f"(c0), "+f"(c1), "+f"(c2), "+f"(c3)
        : "r"(a0), "r"(a1), "r"(a2), "r"(a3), "r"(b0), "r"(b1));
}

__device__ __forceinline__ void ldsm_x4(uint32_t& r0, uint32_t& r1,
                                        uint32_t& r2, uint32_t& r3, uint32_t addr) {
    asm volatile("ldmatrix.sync.aligned.m8n8.x4.shared.b16 {%0,%1,%2,%3}, [%4];"
                 : "=r"(r0), "=r"(r1), "=r"(r2), "=r"(r3) : "r"(addr));
}

__device__ __forceinline__ void cp_async16(uint32_t smem_addr, const void* gptr) {
    asm volatile("cp.async.cg.shared.global [%0], [%1], 16;"
                 :: "r"(smem_addr), "l"(gptr));
}
__device__ __forceinline__ void cp_commit() {
    asm volatile("cp.async.commit_group;");
}
template <int N>
__device__ __forceinline__ void cp_wait() {
    asm volatile("cp.async.wait_group %0;" :: "n"(N));
}

// ---------------------------------------------------------------------------
// Weight transpose + fp16 round, all four weights in one launch.
// ---------------------------------------------------------------------------
__global__ void transpose_half_all(const float* __restrict__ w0, const float* __restrict__ w1,
                                   const float* __restrict__ w2, const float* __restrict__ w3,
                                   __half* __restrict__ out)
{
    const float* W = (blockIdx.z == 0) ? w0 : (blockIdx.z == 1) ? w1
                   : (blockIdx.z == 2) ? w2 : w3;
    __half* dst = out + (size_t)blockIdx.z * CC * CC;

    __shared__ float t[32][33];
    int x = blockIdx.x * 32 + threadIdx.x;
    int y = blockIdx.y * 32 + threadIdx.y;
#pragma unroll
    for (int i = 0; i < 32; i += 8)
        t[threadIdx.y + i][threadIdx.x] = W[(size_t)(y + i) * CC + x];
    __syncthreads();
    x = blockIdx.y * 32 + threadIdx.x;
    y = blockIdx.x * 32 + threadIdx.y;
#pragma unroll
    for (int i = 0; i < 32; i += 8)
        dst[(size_t)(y + i) * CC + x] = __float2half_rn(t[threadIdx.x][threadIdx.y + i]);
}

// ---------------------------------------------------------------------------
// FP16 tensor-core GEMM body. C[M,512] = A[M,512] @ Wt^T + bias
// A_HALF: A fp16 (ldmatrix fragments); else A fp32 (float2 + pack).
// B always fp16, ldmatrix fragments.
// 256 threads, 8 warps (2x4), warp tile 64x32, BK=32, 3-stage cp.async.
// ---------------------------------------------------------------------------
template <bool A_HALF, class OutT>
__device__ __forceinline__
void gemm_body(const void* __restrict__ Araw,
               const __half* __restrict__ Wt,
               const float* __restrict__ bias,
               OutT* __restrict__ C)
{
    extern __shared__ char smem_raw[];
    float*  AsF = reinterpret_cast<float*>(smem_raw);
    __half* Bs  = A_HALF
        ? reinterpret_cast<__half*>(smem_raw + STAGES * A_STAGE_H * 2)
        : reinterpret_cast<__half*>(smem_raw + STAGES * A_STAGE_F * 4);

    const uint32_t as_base = (uint32_t)__cvta_generic_to_shared(smem_raw);
    const uint32_t bs_base = (uint32_t)__cvta_generic_to_shared(Bs);

    const int tid  = threadIdx.x;
    const int warp = tid >> 5;
    const int lane = tid & 31;
    const int g = lane >> 2;
    const int t = lane & 3;
    const int wm = (warp & 1) * 64;
    const int wn = (warp >> 1) * 32;
    const int block_row = blockIdx.y * 128;
    const int block_col = blockIdx.x * 128;

    const float*  AbF = reinterpret_cast<const float*>(Araw)  + (size_t)block_row * CC;
    const __half* AbH = reinterpret_cast<const __half*>(Araw) + (size_t)block_row * CC;
    const __half* Bbase = Wt + (size_t)block_col * CC;

    // ldmatrix per-lane byte offsets within a stage
    const int lt = lane >> 3, lr = lane & 7;
    uint32_t b_lane[2];
#pragma unroll
    for (int np = 0; np < 2; np++)
        b_lane[np] = (uint32_t)(((wn + np * 16 + (lt >> 1) * 8 + lr) * B_STRIDE_H
                                 + (lt & 1) * 8) * 2);
    uint32_t a_lane[4];
    if (A_HALF) {
#pragma unroll
        for (int mi = 0; mi < 4; mi++)
            a_lane[mi] = (uint32_t)(((wm + mi * 16 + (lt & 1) * 8 + lr) * A_STRIDE_H
                                     + (lt >> 1) * 8) * 2);
    }

    const int NT = CC / BKD;   // 16 K-chunks

    auto issue_tile = [&](int it, int stg) {
        const __half* Bn = Bbase + it * BKD;
        const uint32_t b_off = bs_base + (uint32_t)stg * (B_STAGE_H * 2u);
        if (A_HALF) {
            const __half* An = AbH + it * BKD;
            const uint32_t a_off = as_base + (uint32_t)stg * (A_STAGE_H * 2u);
#pragma unroll
            for (int i = 0; i < 2; i++) {
                const int idx = tid + i * 256;
                const int arow = idx >> 2, akq = (idx & 3) * 8;
                cp_async16(a_off + (uint32_t)(arow * A_STRIDE_H + akq) * 2u,
                           An + (size_t)arow * CC + akq);
            }
        } else {
            const float* An = AbF + it * BKD;
            const uint32_t a_off = as_base + (uint32_t)stg * (A_STAGE_F * 4u);
#pragma unroll
            for (int i = 0; i < 4; i++) {
                const int idx = tid + i * 256;
                const int arow = idx >> 3, akq = (idx & 7) * 4;
                cp_async16(a_off + (uint32_t)(arow * A_STRIDE_F + akq) * 4u,
                           An + (size_t)arow * CC + akq);
            }
        }
#pragma unroll
        for (int i = 0; i < 2; i++) {
            const int idx = tid + i * 256;
            const int brow = idx >> 2, bkq = (idx & 3) * 8;
            cp_async16(b_off + (uint32_t)(brow * B_STRIDE_H + bkq) * 2u,
                       Bn + (size_t)brow * CC + bkq);
        }
        cp_commit();
    };

    float acc[4][4][4];
#pragma unroll
    for (int mi = 0; mi < 4; mi++)
#pragma unroll
        for (int ni = 0; ni < 4; ni++)
#pragma unroll
            for (int r = 0; r < 4; r++) acc[mi][ni][r] = 0.0f;

    issue_tile(0, 0);
    issue_tile(1, 1);
    cp_wait<1>();
    __syncthreads();

    int cur = 0;
    for (int it = 0; it < NT; ++it) {
        if (it + 2 < NT) issue_tile(it + 2, (cur + 2) % STAGES);

        const float*   asf     = AsF + cur * A_STAGE_F;
        const uint32_t a_stage = as_base + (uint32_t)cur * (A_STAGE_H * 2u);
        const uint32_t b_stage = bs_base + (uint32_t)cur * (B_STAGE_H * 2u);
#pragma unroll
        for (int khalf = 0; khalf < 2; khalf++) {
            const int k0 = khalf * 16;
            const uint32_t kb = (uint32_t)khalf * 32u;   // 16 halfs = 32 bytes
            uint32_t ar[4][4], br[4][2];
#pragma unroll
            for (int mi = 0; mi < 4; mi++) {
                if (A_HALF) {
                    ldsm_x4(ar[mi][0], ar[mi][1], ar[mi][2], ar[mi][3],
                            a_stage + a_lane[mi] + kb);
                } else {
                    const int r0 = (wm + mi * 16 + g) * A_STRIDE_F;
                    const int r8 = r0 + 8 * A_STRIDE_F;
                    const float2 v0 = *reinterpret_cast<const float2*>(asf + r0 + k0 + 2 * t);
                    const float2 v1 = *reinterpret_cast<const float2*>(asf + r8 + k0 + 2 * t);
                    const float2 v2 = *reinterpret_cast<const float2*>(asf + r0 + k0 + 2 * t + 8);
                    const float2 v3 = *reinterpret_cast<const float2*>(asf + r8 + k0 + 2 * t + 8);
                    ar[mi][0] = pack_h2(v0.x, v0.y);
                    ar[mi][1] = pack_h2(v1.x, v1.y);
                    ar[mi][2] = pack_h2(v2.x, v2.y);
                    ar[mi][3] = pack_h2(v3.x, v3.y);
                }
            }
#pragma unroll
            for (int np = 0; np < 2; np++)
                ldsm_x4(br[2 * np][0], br[2 * np][1], br[2 * np + 1][0], br[2 * np + 1][1],
                        b_stage + b_lane[np] + kb);
#pragma unroll
            for (int mi = 0; mi < 4; mi++)
#pragma unroll
                for (int ni = 0; ni < 4; ni++)
                    mma_f16(acc[mi][ni][0], acc[mi][ni][1], acc[mi][ni][2], acc[mi][ni][3],
                            ar[mi][0], ar[mi][1], ar[mi][2], ar[mi][3],
                            br[ni][0], br[ni][1]);
        }

        cp_wait<1>();
        __syncthreads();
        cur = (cur + 1) % STAGES;
    }

    // Epilogue
#pragma unroll
    for (int mi = 0; mi < 4; mi++) {
        const int row0 = block_row + wm + mi * 16 + g;
#pragma unroll
        for (int ni = 0; ni < 4; ni++) {
            const int col0 = block_col + wn + ni * 8 + t * 2;
            const float2 b2 = *reinterpret_cast<const float2*>(bias + col0);
            const float x0 = acc[mi][ni][0] + b2.x;
            const float y0 = acc[mi][ni][1] + b2.y;
            const float x1 = acc[mi][ni][2] + b2.x;
            const float y1 = acc[mi][ni][3] + b2.y;
            if (sizeof(OutT) == 2) {
                __half* Ch = reinterpret_cast<__half*>(C);
                *reinterpret_cast<__half2*>(Ch + (size_t)row0 * CC + col0)
                    = __floats2half2_rn(x0, y0);
                *reinterpret_cast<__half2*>(Ch + (size_t)(row0 + 8) * CC + col0)
                    = __floats2half2_rn(x1, y1);
            } else {
                float* Cf = reinterpret_cast<float*>(C);
                *reinterpret_cast<float2*>(Cf + (size_t)row0 * CC + col0)
                    = make_float2(x0, y0);
                *reinterpret_cast<float2*>(Cf + (size_t)(row0 + 8) * CC + col0)
                    = make_float2(x1, y1);
            }
        }
    }
}

// QKV: A fp32, out fp16; blockIdx.z selects triple
__global__ __launch_bounds__(256, 2)
void hgemm_qkv(const float* __restrict__ q, const float* __restrict__ k,
               const float* __restrict__ v,
               const __half* __restrict__ wt,
               const float* __restrict__ bq, const float* __restrict__ bk,
               const float* __restrict__ bv,
               __half* __restrict__ qh, __half* __restrict__ kh,
               __half* __restrict__ vh)
{
    const int z = blockIdx.z;
    const float*  A    = (z == 0) ? q  : (z == 1) ? k  : v;
    const __half* W    = wt + (size_t)z * CC * CC;
    const float*  bias = (z == 0) ? bq : (z == 1) ? bk : bv;
    __half*       C    = (z == 0) ? qh : (z == 1) ? kh : vh;
    gemm_body<false, __half>(A, W, bias, C);
}

// Output GEMM: A fp16 (att), out fp32
__global__ __launch_bounds__(256, 2)
void hgemm_out(const __half* __restrict__ A, const __half* __restrict__ W,
               const float* __restrict__ bias, float* __restrict__ C)
{
    gemm_body<true, float>(A, W, bias, C);
}

// ---------------------------------------------------------------------------
// Neighborhood attention on fp16 tensors, fp32 math, fp16 output.
// Lane layout: qi = lane>>3 (4 queries/warp), d8 = (lane&7)*8.
// ---------------------------------------------------------------------------
__device__ __forceinline__ void ld8h(const __half* p, float* f) {
    const uint4 u = *reinterpret_cast<const uint4*>(p);
    const __half2* h = reinterpret_cast<const __half2*>(&u);
#pragma unroll
    for (int i = 0; i < 4; i++) {
        const float2 v = __half22float2(h[i]);
        f[2 * i] = v.x; f[2 * i + 1] = v.y;
    }
}

__global__ __launch_bounds__(256)
void natt_kernel(const __half* __restrict__ qh,
                 const __half* __restrict__ kh,
                 const __half* __restrict__ vh,
                 const float* __restrict__ rpb,
                 __half* __restrict__ out)
{
    const int bi0  = blockIdx.x * 4;
    const int h    = threadIdx.x >> 5;
    const int lane = threadIdx.x & 31;
    const int qi   = lane >> 3;
    const int d8   = (lane & 7) * 8;

    const int bi = bi0 + qi;
    const int i  = bi & (LL - 1);

    int start = i - RR;
    if (start < 0) start = 0;
    if (start > LL - KK) start = LL - KK;

    const size_t qoff = (size_t)bi * CC + h * DH + d8;
    float qv[8];
    ld8h(qh + qoff, qv);
#pragma unroll
    for (int d = 0; d < 8; d++) qv[d] *= SCALE;

    const size_t nbase = (size_t)(bi - i + start) * CC + h * DH + d8;
    const int bias_off = h * NBIAS + (start - i + (KK - 1));

    float s[KK];
#pragma unroll
    for (int k = 0; k < KK; k++) {
        float kv[8];
        ld8h(kh + nbase + (size_t)k * CC, kv);
        float d = qv[0] * kv[0];
#pragma unroll
        for (int dd = 1; dd < 8; dd++) d = fmaf(qv[dd], kv[dd], d);
        d += __shfl_xor_sync(0xffffffffu, d, 1);
        d += __shfl_xor_sync(0xffffffffu, d, 2);
        d += __shfl_xor_sync(0xffffffffu, d, 4);
        s[k] = d + rpb[bias_off + k];
    }

    float m = s[0];
#pragma unroll
    for (int k = 1; k < KK; k++) m = fmaxf(m, s[k]);
    float sum = 0.0f;
#pragma unroll
    for (int k = 0; k < KK; k++) { s[k] = __expf(s[k] - m); sum += s[k]; }
    const float inv = 1.0f / sum;

    float o[8] = {0.f, 0.f, 0.f, 0.f, 0.f, 0.f, 0.f, 0.f};
#pragma unroll
    for (int k = 0; k < KK; k++) {
        float vv[8];
        ld8h(vh + nbase + (size_t)k * CC, vv);
        const float p = s[k] * inv;
#pragma unroll
        for (int dd = 0; dd < 8; dd++) o[dd] = fmaf(p, vv[dd], o[dd]);
    }

    uint4 u;
    __half2* hp = reinterpret_cast<__half2*>(&u);
#pragma unroll
    for (int ii = 0; ii < 4; ii++)
        hp[ii] = __floats2half2_rn(o[2 * ii], o[2 * ii + 1]);
    *reinterpret_cast<uint4*>(out + qoff) = u;
}

// ---------------------------------------------------------------------------
// Launch. Inputs: q, k, v, Wq, bq, Wk, bk, Wv, bv, rpb, Wo, bo
// ---------------------------------------------------------------------------
extern "C" void kernel_launch(void* const* d_in, const int* in_sizes, int n_in,
                              void* d_out, int out_size)
{
    const float* q   = (const float*)d_in[0];
    const float* k   = (const float*)d_in[1];
    const float* v   = (const float*)d_in[2];
    const float* Wq  = (const float*)d_in[3];
    const float* bq  = (const float*)d_in[4];
    const float* Wk  = (const float*)d_in[5];
    const float* bk  = (const float*)d_in[6];
    const float* Wv  = (const float*)d_in[7];
    const float* bv  = (const float*)d_in[8];
    const float* rpb = (const float*)d_in[9];
    const float* Wo  = (const float*)d_in[10];
    const float* bo  = (const float*)d_in[11];
    float* out = (float*)d_out;

    __half *qh, *kh, *vh, *att, *wt;
    cudaGetSymbolAddress((void**)&qh,  g_qh);
    cudaGetSymbolAddress((void**)&kh,  g_kh);
    cudaGetSymbolAddress((void**)&vh,  g_vh);
    cudaGetSymbolAddress((void**)&att, g_att);
    cudaGetSymbolAddress((void**)&wt,  g_wt);

    cudaFuncSetAttribute(hgemm_qkv,
                         cudaFuncAttributeMaxDynamicSharedMemorySize, SMEM_BYTES_F32A);
    cudaFuncSetAttribute(hgemm_out,
                         cudaFuncAttributeMaxDynamicSharedMemorySize, SMEM_BYTES_F16A);

    dim3 tblk(32, 8), tgrid(CC / 32, CC / 32, 4);
    transpose_half_all<<<tgrid, tblk>>>(Wq, Wk, Wv, Wo, wt);

    dim3 qkv_grid(CC / 128, M_TOTAL / 128, 3);
    hgemm_qkv<<<qkv_grid, 256, SMEM_BYTES_F32A>>>(q, k, v, wt, bq, bk, bv, qh, kh, vh);

    natt_kernel<<<M_TOTAL / 4, 256>>>(qh, kh, vh, rpb, att);

    dim3 gemm_grid(CC / 128, M_TOTAL / 128);
    hgemm_out<<<gemm_grid, 256, SMEM_BYTES_F16A>>>(att, wt + 3 * CC * CC, bo, out);
}

// round 16
// speedup vs baseline: 1.0133x; 1.0133x over previous
#include <cuda_runtime.h>
#include <cuda_fp16.h>
#include <cstdint>

// Problem constants
#define BB 2
#define LL 4096
#define CC 512
#define HH 8
#define KK 13
#define DH 64
#define RR 6              // K/2
#define NBIAS 25          // 2K-1
#define SCALE 0.125f      // DH^-0.5

#define M_TOTAL (BB * LL)   // 8192 rows per GEMM

// ---- QKV GEMM tiling (BK=32, fp32 A) — identical to R14-passing config ----
#define BKD 32
#define A_STRIDE_F 40       // fp32 A: floats/row; 160B
#define B_STRIDE_H 40       // fp16 B: halfs/row; 80B
#define STAGES 3
#define A_STAGE_F (128 * A_STRIDE_F)   // 5120 floats (20480 B)
#define B_STAGE_H (128 * B_STRIDE_H)   // 5120 halfs  (10240 B)
#define SMEM_BYTES_F32A (STAGES * (A_STAGE_F * 4 + B_STAGE_H * 2))  // 92160

// ---- Output GEMM tiling (BK=64, fp16 A) ----
#define BKD64 64
#define STR64 72            // halfs/row = 144B; ldsm banks r*36%32 disjoint
#define A64_STAGE_H (128 * STR64)      // 9216 halfs = 18432 B
#define B64_STAGE_H (128 * STR64)      // 18432 B
#define SMEM_BYTES_64 (STAGES * (A64_STAGE_H + B64_STAGE_H) * 2)    // 110592

// ---------------------------------------------------------------------------
// Scratch (no cudaMalloc). cp.async global sources must be 16B-aligned.
// NOTE: no fp16 input-conversion arrays — that subsystem is quarantined
// (perfectly correlated with container failures in R12/R13/R15).
// ---------------------------------------------------------------------------
__device__ __align__(16) __half g_qh[M_TOTAL * CC];
__device__ __align__(16) __half g_kh[M_TOTAL * CC];
__device__ __align__(16) __half g_vh[M_TOTAL * CC];
__device__ __align__(16) __half g_att[M_TOTAL * CC];
__device__ __align__(16) __half g_wt[4][CC * CC];   // fp16 weights, transposed [N][K]

// ---------------------------------------------------------------------------
// Helpers
// ---------------------------------------------------------------------------
__device__ __forceinline__ uint32_t pack_h2(float lo, float hi) {
    __half2 h = __floats2half2_rn(lo, hi);
    return *reinterpret_cast<uint32_t*>(&h);
}

__device__ __forceinline__ void mma_f16(float& c0, float& c1, float& c2, float& c3,
                                        uint32_t a0, uint32_t a1, uint32_t a2, uint32_t a3,
                                        uint32_t b0, uint32_t b1) {
    asm volatile(
        "mma.sync.aligned.m16n8k16.row.col.f32.f16.f16.f32 "
        "{%0,%1,%2,%3}, {%4,%5,%6,%7}, {%8,%9}, {%0,%1,%2,%3};"
        : "+f"(c0), "+f"(c1), "+f"(c2), "+f"(c3)
        : "r"(a0), "r"(a1), "r"(a2), "r"(a3), "r"(b0), "r"(b1));
}

__device__ __forceinline__ void ldsm_x4(uint32_t& r0, uint32_t& r1,
                                        uint32_t& r2, uint32_t& r3, uint32_t addr) {
    asm volatile("ldmatrix.sync.aligned.m8n8.x4.shared.b16 {%0,%1,%2,%3}, [%4];"
                 : "=r"(r0), "=r"(r1), "=r"(r2), "=r"(r3) : "r"(addr));
}

__device__ __forceinline__ void cp_async16(uint32_t smem_addr, const void* gptr) {
    asm volatile("cp.async.cg.shared.global [%0], [%1], 16;"
                 :: "r"(smem_addr), "l"(gptr));
}
__device__ __forceinline__ void cp_commit() {
    asm volatile("cp.async.commit_group;");
}
template <int N>
__device__ __forceinline__ void cp_wait() {
    asm volatile("cp.async.wait_group %0;" :: "n"(N));
}

// ---------------------------------------------------------------------------
// Weight transpose + fp16 round, all four weights in one launch.
// ---------------------------------------------------------------------------
__global__ void transpose_half_all(const float* __restrict__ w0, const float* __restrict__ w1,
                                   const float* __restrict__ w2, const float* __restrict__ w3,
                                   __half* __restrict__ out)
{
    const float* W = (blockIdx.z == 0) ? w0 : (blockIdx.z == 1) ? w1
                   : (blockIdx.z == 2) ? w2 : w3;
    __half* dst = out + (size_t)blockIdx.z * CC * CC;

    __shared__ float t[32][33];
    int x = blockIdx.x * 32 + threadIdx.x;
    int y = blockIdx.y * 32 + threadIdx.y;
#pragma unroll
    for (int i = 0; i < 32; i += 8)
        t[threadIdx.y + i][threadIdx.x] = W[(size_t)(y + i) * CC + x];
    __syncthreads();
    x = blockIdx.y * 32 + threadIdx.x;
    y = blockIdx.x * 32 + threadIdx.y;
#pragma unroll
    for (int i = 0; i < 32; i += 8)
        dst[(size_t)(y + i) * CC + x] = __float2half_rn(t[threadIdx.x][threadIdx.y + i]);
}

// ---------------------------------------------------------------------------
// QKV GEMM body (BK=32, fp32 A with pack, fp16 B via ldmatrix) — R14-passing.
// ---------------------------------------------------------------------------
__device__ __forceinline__
void gemm_body_qkv(const float* __restrict__ A,
                   const __half* __restrict__ Wt,
                   const float* __restrict__ bias,
                   __half* __restrict__ C)
{
    extern __shared__ char smem_raw[];
    float*  AsF = reinterpret_cast<float*>(smem_raw);
    __half* Bs  = reinterpret_cast<__half*>(smem_raw + STAGES * A_STAGE_F * 4);

    const uint32_t as_base = (uint32_t)__cvta_generic_to_shared(smem_raw);
    const uint32_t bs_base = (uint32_t)__cvta_generic_to_shared(Bs);

    const int tid  = threadIdx.x;
    const int warp = tid >> 5;
    const int lane = tid & 31;
    const int g = lane >> 2;
    const int t = lane & 3;
    const int wm = (warp & 1) * 64;
    const int wn = (warp >> 1) * 32;
    const int block_row = blockIdx.y * 128;
    const int block_col = blockIdx.x * 128;

    const float*  Ab = A  + (size_t)block_row * CC;
    const __half* Bb = Wt + (size_t)block_col * CC;

    const int lt = lane >> 3, lr = lane & 7;
    uint32_t b_lane[2];
#pragma unroll
    for (int np = 0; np < 2; np++)
        b_lane[np] = (uint32_t)(((wn + np * 16 + (lt >> 1) * 8 + lr) * B_STRIDE_H
                                 + (lt & 1) * 8) * 2);

    const int NT = CC / BKD;   // 16

    auto issue_tile = [&](int it, int stg) {
        const float*  An = Ab + it * BKD;
        const __half* Bn = Bb + it * BKD;
        const uint32_t a_off = as_base + (uint32_t)stg * (A_STAGE_F * 4u);
        const uint32_t b_off = bs_base + (uint32_t)stg * (B_STAGE_H * 2u);
#pragma unroll
        for (int i = 0; i < 4; i++) {
            const int idx = tid + i * 256;
            const int arow = idx >> 3, akq = (idx & 7) * 4;
            cp_async16(a_off + (uint32_t)(arow * A_STRIDE_F + akq) * 4u,
                       An + (size_t)arow * CC + akq);
        }
#pragma unroll
        for (int i = 0; i < 2; i++) {
            const int idx = tid + i * 256;
            const int brow = idx >> 2, bkq = (idx & 3) * 8;
            cp_async16(b_off + (uint32_t)(brow * B_STRIDE_H + bkq) * 2u,
                       Bn + (size_t)brow * CC + bkq);
        }
        cp_commit();
    };

    float acc[4][4][4];
#pragma unroll
    for (int mi = 0; mi < 4; mi++)
#pragma unroll
        for (int ni = 0; ni < 4; ni++)
#pragma unroll
            for (int r = 0; r < 4; r++) acc[mi][ni][r] = 0.0f;

    issue_tile(0, 0);
    issue_tile(1, 1);
    cp_wait<1>();
    __syncthreads();

    int cur = 0;
    for (int it = 0; it < NT; ++it) {
        if (it + 2 < NT) issue_tile(it + 2, (cur + 2) % STAGES);

        const float*   asf     = AsF + cur * A_STAGE_F;
        const uint32_t b_stage = bs_base + (uint32_t)cur * (B_STAGE_H * 2u);
#pragma unroll
        for (int khalf = 0; khalf < 2; khalf++) {
            const int k0 = khalf * 16;
            const uint32_t kb = (uint32_t)khalf * 32u;
            uint32_t ar[4][4], br[4][2];
#pragma unroll
            for (int mi = 0; mi < 4; mi++) {
                const int r0 = (wm + mi * 16 + g) * A_STRIDE_F;
                const int r8 = r0 + 8 * A_STRIDE_F;
                const float2 v0 = *reinterpret_cast<const float2*>(asf + r0 + k0 + 2 * t);
                const float2 v1 = *reinterpret_cast<const float2*>(asf + r8 + k0 + 2 * t);
                const float2 v2 = *reinterpret_cast<const float2*>(asf + r0 + k0 + 2 * t + 8);
                const float2 v3 = *reinterpret_cast<const float2*>(asf + r8 + k0 + 2 * t + 8);
                ar[mi][0] = pack_h2(v0.x, v0.y);
                ar[mi][1] = pack_h2(v1.x, v1.y);
                ar[mi][2] = pack_h2(v2.x, v2.y);
                ar[mi][3] = pack_h2(v3.x, v3.y);
            }
#pragma unroll
            for (int np = 0; np < 2; np++)
                ldsm_x4(br[2 * np][0], br[2 * np][1], br[2 * np + 1][0], br[2 * np + 1][1],
                        b_stage + b_lane[np] + kb);
#pragma unroll
            for (int mi = 0; mi < 4; mi++)
#pragma unroll
                for (int ni = 0; ni < 4; ni++)
                    mma_f16(acc[mi][ni][0], acc[mi][ni][1], acc[mi][ni][2], acc[mi][ni][3],
                            ar[mi][0], ar[mi][1], ar[mi][2], ar[mi][3],
                            br[ni][0], br[ni][1]);
        }

        cp_wait<1>();
        __syncthreads();
        cur = (cur + 1) % STAGES;
    }

#pragma unroll
    for (int mi = 0; mi < 4; mi++) {
        const int row0 = block_row + wm + mi * 16 + g;
#pragma unroll
        for (int ni = 0; ni < 4; ni++) {
            const int col0 = block_col + wn + ni * 8 + t * 2;
            const float2 b2 = *reinterpret_cast<const float2*>(bias + col0);
            *reinterpret_cast<__half2*>(C + (size_t)row0 * CC + col0)
                = __floats2half2_rn(acc[mi][ni][0] + b2.x, acc[mi][ni][1] + b2.y);
            *reinterpret_cast<__half2*>(C + (size_t)(row0 + 8) * CC + col0)
                = __floats2half2_rn(acc[mi][ni][2] + b2.x, acc[mi][ni][3] + b2.y);
        }
    }
}

__global__ __launch_bounds__(256, 2)
void hgemm_qkv(const float* __restrict__ q, const float* __restrict__ k,
               const float* __restrict__ v,
               const __half* __restrict__ wt,
               const float* __restrict__ bq, const float* __restrict__ bk,
               const float* __restrict__ bv,
               __half* __restrict__ qh, __half* __restrict__ kh,
               __half* __restrict__ vh)
{
    const int z = blockIdx.z;
    const float*  A    = (z == 0) ? q  : (z == 1) ? k  : v;
    const __half* W    = wt + (size_t)z * CC * CC;
    const float*  bias = (z == 0) ? bq : (z == 1) ? bk : bv;
    __half*       C    = (z == 0) ? qh : (z == 1) ? kh : vh;
    gemm_body_qkv(A, W, bias, C);
}

// ---------------------------------------------------------------------------
// Output GEMM (BK=64, all-fp16 A/B via ldmatrix): 8 barrier pairs per CTA.
// ---------------------------------------------------------------------------
__global__ __launch_bounds__(256, 2)
void hgemm_out(const __half* __restrict__ A, const __half* __restrict__ Wt,
               const float* __restrict__ bias, float* __restrict__ C)
{
    extern __shared__ char smem_raw[];
    const uint32_t as_base = (uint32_t)__cvta_generic_to_shared(smem_raw);
    const uint32_t bs_base = as_base + STAGES * A64_STAGE_H * 2;

    const int tid  = threadIdx.x;
    const int warp = tid >> 5;
    const int lane = tid & 31;
    const int g = lane >> 2;
    const int t = lane & 3;
    const int wm = (warp & 1) * 64;
    const int wn = (warp >> 1) * 32;
    const int block_row = blockIdx.y * 128;
    const int block_col = blockIdx.x * 128;

    const __half* Ab = A  + (size_t)block_row * CC;
    const __half* Bb = Wt + (size_t)block_col * CC;

    const int lt = lane >> 3, lr = lane & 7;
    uint32_t a_lane[4], b_lane[2];
#pragma unroll
    for (int mi = 0; mi < 4; mi++)
        a_lane[mi] = (uint32_t)(((wm + mi * 16 + (lt & 1) * 8 + lr) * STR64
                                 + (lt >> 1) * 8) * 2);
#pragma unroll
    for (int np = 0; np < 2; np++)
        b_lane[np] = (uint32_t)(((wn + np * 16 + (lt >> 1) * 8 + lr) * STR64
                                 + (lt & 1) * 8) * 2);

    const int NT = CC / BKD64;   // 8

    auto issue_tile = [&](int it, int stg) {
        const __half* An = Ab + it * BKD64;
        const __half* Bn = Bb + it * BKD64;
        const uint32_t a_off = as_base + (uint32_t)stg * (A64_STAGE_H * 2u);
        const uint32_t b_off = bs_base + (uint32_t)stg * (B64_STAGE_H * 2u);
#pragma unroll
        for (int i = 0; i < 4; i++) {
            const int idx = tid + i * 256;              // 0..1023
            const int row = idx >> 3, kq = (idx & 7) * 8;
            const uint32_t so = (uint32_t)((row * STR64 + kq) * 2);
            cp_async16(a_off + so, An + (size_t)row * CC + kq);
            cp_async16(b_off + so, Bn + (size_t)row * CC + kq);
        }
        cp_commit();
    };

    float acc[4][4][4];
#pragma unroll
    for (int mi = 0; mi < 4; mi++)
#pragma unroll
        for (int ni = 0; ni < 4; ni++)
#pragma unroll
            for (int r = 0; r < 4; r++) acc[mi][ni][r] = 0.0f;

    issue_tile(0, 0);
    issue_tile(1, 1);
    cp_wait<1>();
    __syncthreads();

    int cur = 0;
    for (int it = 0; it < NT; ++it) {
        if (it + 2 < NT) issue_tile(it + 2, (cur + 2) % STAGES);

        const uint32_t a_stage = as_base + (uint32_t)cur * (A64_STAGE_H * 2u);
        const uint32_t b_stage = bs_base + (uint32_t)cur * (B64_STAGE_H * 2u);
#pragma unroll
        for (int khalf = 0; khalf < 4; khalf++) {
            const uint32_t kb = (uint32_t)khalf * 32u;
            uint32_t ar[4][4], br[4][2];
#pragma unroll
            for (int mi = 0; mi < 4; mi++)
                ldsm_x4(ar[mi][0], ar[mi][1], ar[mi][2], ar[mi][3],
                        a_stage + a_lane[mi] + kb);
#pragma unroll
            for (int np = 0; np < 2; np++)
                ldsm_x4(br[2 * np][0], br[2 * np][1], br[2 * np + 1][0], br[2 * np + 1][1],
                        b_stage + b_lane[np] + kb);
#pragma unroll
            for (int mi = 0; mi < 4; mi++)
#pragma unroll
                for (int ni = 0; ni < 4; ni++)
                    mma_f16(acc[mi][ni][0], acc[mi][ni][1], acc[mi][ni][2], acc[mi][ni][3],
                            ar[mi][0], ar[mi][1], ar[mi][2], ar[mi][3],
                            br[ni][0], br[ni][1]);
        }

        cp_wait<1>();
        __syncthreads();
        cur = (cur + 1) % STAGES;
    }

#pragma unroll
    for (int mi = 0; mi < 4; mi++) {
        const int row0 = block_row + wm + mi * 16 + g;
#pragma unroll
        for (int ni = 0; ni < 4; ni++) {
            const int col0 = block_col + wn + ni * 8 + t * 2;
            const float2 b2 = *reinterpret_cast<const float2*>(bias + col0);
            *reinterpret_cast<float2*>(C + (size_t)row0 * CC + col0)
                = make_float2(acc[mi][ni][0] + b2.x, acc[mi][ni][1] + b2.y);
            *reinterpret_cast<float2*>(C + (size_t)(row0 + 8) * CC + col0)
                = make_float2(acc[mi][ni][2] + b2.x, acc[mi][ni][3] + b2.y);
        }
    }
}

// ---------------------------------------------------------------------------
// Neighborhood attention (R14-passing version, unchanged).
// ---------------------------------------------------------------------------
__device__ __forceinline__ void ld8h(const __half* p, float* f) {
    const uint4 u = *reinterpret_cast<const uint4*>(p);
    const __half2* h = reinterpret_cast<const __half2*>(&u);
#pragma unroll
    for (int i = 0; i < 4; i++) {
        const float2 v = __half22float2(h[i]);
        f[2 * i] = v.x; f[2 * i + 1] = v.y;
    }
}

__global__ __launch_bounds__(256)
void natt_kernel(const __half* __restrict__ qh,
                 const __half* __restrict__ kh,
                 const __half* __restrict__ vh,
                 const float* __restrict__ rpb,
                 __half* __restrict__ out)
{
    const int bi0  = blockIdx.x * 4;
    const int h    = threadIdx.x >> 5;
    const int lane = threadIdx.x & 31;
    const int qi   = lane >> 3;
    const int d8   = (lane & 7) * 8;

    const int bi = bi0 + qi;
    const int i  = bi & (LL - 1);

    int start = i - RR;
    if (start < 0) start = 0;
    if (start > LL - KK) start = LL - KK;

    const size_t qoff = (size_t)bi * CC + h * DH + d8;
    float qv[8];
    ld8h(qh + qoff, qv);
#pragma unroll
    for (int d = 0; d < 8; d++) qv[d] *= SCALE;

    const size_t nbase = (size_t)(bi - i + start) * CC + h * DH + d8;
    const int bias_off = h * NBIAS + (start - i + (KK - 1));

    float s[KK];
#pragma unroll
    for (int k = 0; k < KK; k++) {
        float kv[8];
        ld8h(kh + nbase + (size_t)k * CC, kv);
        float d = qv[0] * kv[0];
#pragma unroll
        for (int dd = 1; dd < 8; dd++) d = fmaf(qv[dd], kv[dd], d);
        d += __shfl_xor_sync(0xffffffffu, d, 1);
        d += __shfl_xor_sync(0xffffffffu, d, 2);
        d += __shfl_xor_sync(0xffffffffu, d, 4);
        s[k] = d + rpb[bias_off + k];
    }

    float m = s[0];
#pragma unroll
    for (int k = 1; k < KK; k++) m = fmaxf(m, s[k]);
    float sum = 0.0f;
#pragma unroll
    for (int k = 0; k < KK; k++) { s[k] = __expf(s[k] - m); sum += s[k]; }
    const float inv = 1.0f / sum;

    float o[8] = {0.f, 0.f, 0.f, 0.f, 0.f, 0.f, 0.f, 0.f};
#pragma unroll
    for (int k = 0; k < KK; k++) {
        float vv[8];
        ld8h(vh + nbase + (size_t)k * CC, vv);
        const float p = s[k] * inv;
#pragma unroll
        for (int dd = 0; dd < 8; dd++) o[dd] = fmaf(p, vv[dd], o[dd]);
    }

    uint4 u;
    __half2* hp = reinterpret_cast<__half2*>(&u);
#pragma unroll
    for (int ii = 0; ii < 4; ii++)
        hp[ii] = __floats2half2_rn(o[2 * ii], o[2 * ii + 1]);
    *reinterpret_cast<uint4*>(out + qoff) = u;
}

// ---------------------------------------------------------------------------
// Launch. Inputs: q, k, v, Wq, bq, Wk, bk, Wv, bv, rpb, Wo, bo
// ---------------------------------------------------------------------------
extern "C" void kernel_launch(void* const* d_in, const int* in_sizes, int n_in,
                              void* d_out, int out_size)
{
    const float* q   = (const float*)d_in[0];
    const float* k   = (const float*)d_in[1];
    const float* v   = (const float*)d_in[2];
    const float* Wq  = (const float*)d_in[3];
    const float* bq  = (const float*)d_in[4];
    const float* Wk  = (const float*)d_in[5];
    const float* bk  = (const float*)d_in[6];
    const float* Wv  = (const float*)d_in[7];
    const float* bv  = (const float*)d_in[8];
    const float* rpb = (const float*)d_in[9];
    const float* Wo  = (const float*)d_in[10];
    const float* bo  = (const float*)d_in[11];
    float* out = (float*)d_out;

    __half *qh, *kh, *vh, *att, *wt;
    cudaGetSymbolAddress((void**)&qh,  g_qh);
    cudaGetSymbolAddress((void**)&kh,  g_kh);
    cudaGetSymbolAddress((void**)&vh,  g_vh);
    cudaGetSymbolAddress((void**)&att, g_att);
    cudaGetSymbolAddress((void**)&wt,  g_wt);

    cudaFuncSetAttribute(hgemm_qkv,
                         cudaFuncAttributeMaxDynamicSharedMemorySize, SMEM_BYTES_F32A);
    cudaFuncSetAttribute(hgemm_out,
                         cudaFuncAttributeMaxDynamicSharedMemorySize, SMEM_BYTES_64);

    dim3 tblk(32, 8), tgrid(CC / 32, CC / 32, 4);
    transpose_half_all<<<tgrid, tblk>>>(Wq, Wk, Wv, Wo, wt);

    dim3 qkv_grid(CC / 128, M_TOTAL / 128, 3);
    hgemm_qkv<<<qkv_grid, 256, SMEM_BYTES_F32A>>>(q, k, v, wt, bq, bk, bv, qh, kh, vh);

    natt_kernel<<<M_TOTAL / 4, 256>>>(qh, kh, vh, rpb, att);

    dim3 gemm_grid(CC / 128, M_TOTAL / 128);
    hgemm_out<<<gemm_grid, 256, SMEM_BYTES_64>>>(att, wt + 3 * CC * CC, bo, out);
}